// round 1
// baseline (speedup 1.0000x reference)
#include <cuda_runtime.h>
#include <cstdint>

#define B 32
#define D 128
#define DIN 2048
#define A_DIM 7
#define TOPK 5
#define RTILE 64
#define MAX_TILES 8192

__device__ __align__(16) float g_q[B * D];
__device__ float g_qnorm[B];
__device__ unsigned long long g_cand[(size_t)MAX_TILES * B * TOPK];

__device__ __forceinline__ unsigned long long ullmin2(unsigned long long a, unsigned long long b) {
    return a < b ? a : b;
}

// order-preserving float->u32 (handles negatives)
__device__ __forceinline__ unsigned long long pack_key(float v, unsigned idx) {
    unsigned u = __float_as_uint(v);
    u = (u & 0x80000000u) ? ~u : (u | 0x80000000u);
    return ((unsigned long long)u << 32) | (unsigned long long)idx;
}

__device__ __forceinline__ float unpack_val(unsigned long long key) {
    unsigned u = (unsigned)(key >> 32);
    u = (u & 0x80000000u) ? (u & 0x7fffffffu) : ~u;
    return __uint_as_float(u);
}

// ---------------- Kernel A: encoder GEMM + query norms ----------------
__global__ void encoder_kernel(const float* __restrict__ x,
                               const float* __restrict__ W,
                               const float* __restrict__ bvec) {
    __shared__ float xs[DIN];
    __shared__ float red[4];
    int row = blockIdx.x;
    int d = threadIdx.x;  // 128 threads
    for (int i = d; i < DIN; i += 128) xs[i] = x[row * DIN + i];
    __syncthreads();
    float acc = 0.f;
#pragma unroll 8
    for (int i = 0; i < DIN; i++) acc = fmaf(xs[i], W[i * D + d], acc);
    acc += bvec[d];
    g_q[row * D + d] = acc;
    float s = acc * acc;
#pragma unroll
    for (int o = 16; o > 0; o >>= 1) s += __shfl_xor_sync(0xffffffffu, s, o);
    if ((d & 31) == 0) red[d >> 5] = s;
    __syncthreads();
    if (d == 0) g_qnorm[row] = red[0] + red[1] + red[2] + red[3];
}

// ---------------- Kernel B: fused distance + per-block top-5 ----------------
__global__ __launch_bounds__(256, 4)
void dist_topk_kernel(const float* __restrict__ reps, int N) {
    __shared__ float4 Qs[32 * 32];   // 16 KB, swizzled
    __shared__ float4 Rs[64 * 32];   // 32 KB, swizzled (reused for rnorm+dist)
    float* RsF = (float*)Rs;

    int tid = threadIdx.x;
    int tile = blockIdx.x;
    long base = (long)tile * RTILE;

    // Load Q (32 rows x 32 float4 chunks), swizzle chunk c of row r to (c+r)&31
    const float4* q4 = (const float4*)g_q;
    for (int idx = tid; idx < 32 * 32; idx += 256) {
        int r = idx >> 5, c = idx & 31;
        Qs[r * 32 + ((c + r) & 31)] = q4[r * 32 + c];
    }
    // Load R tile (64 rows x 32 chunks), same swizzle; OOB rows -> zeros
    const float4* reps4 = (const float4*)reps;
#pragma unroll
    for (int it = 0; it < (64 * 32) / 256; it++) {
        int idx = tid + it * 256;
        int r = idx >> 5, c = idx & 31;
        long grow = base + r;
        float4 v = make_float4(0.f, 0.f, 0.f, 0.f);
        if (grow < (long)N) v = reps4[grow * 32 + c];
        Rs[r * 32 + ((c + r) & 31)] = v;
    }
    __syncthreads();

    int qg = tid & 7;        // 8 q-groups
    int rg = tid >> 3;       // 32 r-groups
    int r0 = rg * 2;

    float acc[4][2];
#pragma unroll
    for (int j = 0; j < 4; j++)
#pragma unroll
        for (int i = 0; i < 2; i++) acc[j][i] = 0.f;

#pragma unroll 4
    for (int c = 0; c < 32; c++) {
        float4 qf[4], rf[2];
#pragma unroll
        for (int j = 0; j < 4; j++) {
            int q = qg + 8 * j;
            qf[j] = Qs[q * 32 + ((c + q) & 31)];
        }
#pragma unroll
        for (int i = 0; i < 2; i++) {
            int r = r0 + i;
            rf[i] = Rs[r * 32 + ((c + r) & 31)];
        }
#pragma unroll
        for (int j = 0; j < 4; j++)
#pragma unroll
            for (int i = 0; i < 2; i++) {
                acc[j][i] = fmaf(qf[j].x, rf[i].x, acc[j][i]);
                acc[j][i] = fmaf(qf[j].y, rf[i].y, acc[j][i]);
                acc[j][i] = fmaf(qf[j].z, rf[i].z, acc[j][i]);
                acc[j][i] = fmaf(qf[j].w, rf[i].w, acc[j][i]);
            }
    }
    __syncthreads();

    // rnorm per tile row (threads 0..63), from swizzled Rs while still intact
    float rn = 0.f;
    if (tid < 64) {
#pragma unroll 8
        for (int c = 0; c < 32; c++) {
            float4 v = Rs[tid * 32 + ((c + tid) & 31)];
            rn = fmaf(v.x, v.x, fmaf(v.y, v.y, fmaf(v.z, v.z, fmaf(v.w, v.w, rn))));
        }
        if (base + tid >= (long)N) rn = 1e30f;  // OOB: never selected
    }
    __syncthreads();
    // Overlay scratch onto Rs: rnorm at RsF[0..63], dist at RsF[64 + q*64 + r]
    if (tid < 64) RsF[tid] = rn;
    __syncthreads();
    float* dist = RsF + 64;
#pragma unroll
    for (int j = 0; j < 4; j++) {
        int q = qg + 8 * j;
#pragma unroll
        for (int i = 0; i < 2; i++) {
            int r = r0 + i;
            dist[q * 64 + r] = RsF[r] - 2.f * acc[j][i];  // |r|^2 - 2 q.r
        }
    }
    __syncthreads();

    // Per-q top-5 over the 64 tile rows: warp w handles queries 4w..4w+3
    int wid = tid >> 5, lane = tid & 31;
    unsigned long long* candOut = g_cand + ((long)tile * B) * TOPK;
    for (int q = wid * 4; q < wid * 4 + 4; q++) {
        unsigned long long k0 = pack_key(dist[q * 64 + lane], (unsigned)(base + lane));
        unsigned long long k1 = pack_key(dist[q * 64 + lane + 32], (unsigned)(base + lane + 32));
#pragma unroll
        for (int s = 0; s < TOPK; s++) {
            unsigned long long m = ullmin2(k0, k1);
#pragma unroll
            for (int o = 16; o > 0; o >>= 1)
                m = ullmin2(m, __shfl_xor_sync(0xffffffffu, m, o));
            if (lane == 0) candOut[q * TOPK + s] = m;
            if (k0 == m) k0 = ~0ull;
            if (k1 == m) k1 = ~0ull;
        }
    }
}

// ---------------- Kernel C: global merge + softmax + action gather ----------------
__global__ void final_kernel(const float* __restrict__ actions,
                             float* __restrict__ out, int ntiles) {
    __shared__ unsigned long long sh[256 * TOPK];
    __shared__ float dshare[TOPK];
    __shared__ unsigned ishare[TOPK];
    int q = blockIdx.x, tid = threadIdx.x;
    int total = ntiles * TOPK;

    unsigned long long loc[TOPK];
#pragma unroll
    for (int i = 0; i < TOPK; i++) loc[i] = ~0ull;

    for (int i = tid; i < total; i += 256) {
        int tile = i / TOPK, s = i - tile * TOPK;
        unsigned long long key = g_cand[((long)tile * B + q) * TOPK + s];
        if (key < loc[TOPK - 1]) {
            loc[TOPK - 1] = key;
#pragma unroll
            for (int j = TOPK - 1; j > 0; j--) {
                if (loc[j] < loc[j - 1]) {
                    unsigned long long t = loc[j]; loc[j] = loc[j - 1]; loc[j - 1] = t;
                }
            }
        }
    }
#pragma unroll
    for (int i = 0; i < TOPK; i++) sh[tid * TOPK + i] = loc[i];
    __syncthreads();

    // tree-merge sorted 5-lists
    for (int stride = 128; stride >= 1; stride >>= 1) {
        if (tid < stride) {
            unsigned long long a[TOPK], b[TOPK], res[TOPK];
#pragma unroll
            for (int i = 0; i < TOPK; i++) { a[i] = sh[tid * TOPK + i]; b[i] = sh[(tid + stride) * TOPK + i]; }
            int ia = 0, ib = 0;
#pragma unroll
            for (int i = 0; i < TOPK; i++) {
                if (a[ia] <= b[ib]) res[i] = a[ia++];
                else res[i] = b[ib++];
            }
#pragma unroll
            for (int i = 0; i < TOPK; i++) sh[tid * TOPK + i] = res[i];
        }
        __syncthreads();
    }

    if (tid < TOPK) {
        unsigned long long key = sh[tid];
        float v = unpack_val(key);
        float sq = g_qnorm[q] + v;
        dshare[tid] = sqrtf(fmaxf(sq, 1e-12f));
        ishare[tid] = (unsigned)(key & 0xffffffffull);
    }
    __syncthreads();

    if (tid < A_DIM) {
        float mx = -1e30f;
#pragma unroll
        for (int i = 0; i < TOPK; i++) mx = fmaxf(mx, -dshare[i]);
        float w[TOPK], sum = 0.f;
#pragma unroll
        for (int i = 0; i < TOPK; i++) { w[i] = expf(-dshare[i] - mx); sum += w[i]; }
        float o = 0.f;
#pragma unroll
        for (int i = 0; i < TOPK; i++)
            o += (w[i] / sum) * actions[(long)ishare[i] * A_DIM + tid];
        out[q * A_DIM + tid] = o;
    }
}

extern "C" void kernel_launch(void* const* d_in, const int* in_sizes, int n_in,
                              void* d_out, int out_size) {
    const float* x       = (const float*)d_in[0];
    const float* W_enc   = (const float*)d_in[1];
    const float* b_enc   = (const float*)d_in[2];
    const float* reps    = (const float*)d_in[3];
    const float* actions = (const float*)d_in[4];
    // d_in[5] = k (always 5 for this problem; TOPK hardcoded)

    int N = in_sizes[3] / D;
    int ntiles = (N + RTILE - 1) / RTILE;

    encoder_kernel<<<B, 128>>>(x, W_enc, b_enc);
    dist_topk_kernel<<<ntiles, 256>>>(reps, N);
    final_kernel<<<B, 256>>>(actions, (float*)d_out, ntiles);
}

// round 3
// speedup vs baseline: 1.8707x; 1.8707x over previous
#include <cuda_runtime.h>
#include <cstdint>

#define B 32
#define D 128
#define DIN 2048
#define A_DIM 7
#define TOPK 5
#define RTILE 256
#define KSLICES 16
#define MAX_TILES 8192

__device__ __align__(16) float g_q[B * D];
__device__ __align__(16) float g_qpart[KSLICES * B * D];
__device__ float g_qnorm[B];
// layout: [q][tile*TOPK + s]
__device__ unsigned long long g_cand[(size_t)B * MAX_TILES * TOPK];

__device__ __forceinline__ unsigned long long ullmin2(unsigned long long a, unsigned long long b) {
    return a < b ? a : b;
}

__device__ __forceinline__ unsigned long long pack_key(float v, unsigned idx) {
    unsigned u = __float_as_uint(v);
    u = (u & 0x80000000u) ? ~u : (u | 0x80000000u);
    return ((unsigned long long)u << 32) | (unsigned long long)idx;
}

__device__ __forceinline__ float unpack_val(unsigned long long key) {
    unsigned u = (unsigned)(key >> 32);
    u = (u & 0x80000000u) ? (u & 0x7fffffffu) : ~u;
    return __uint_as_float(u);
}

// ---------------- Kernel A1: encoder GEMM partials (split-K) ----------------
__global__ void encoder_part_kernel(const float* __restrict__ x,
                                    const float* __restrict__ W) {
    __shared__ float xs[DIN / KSLICES];   // 128 floats
    int row = blockIdx.x;
    int ks = blockIdx.y;
    int d = threadIdx.x;
    int k0 = ks * (DIN / KSLICES);
    xs[d] = x[row * DIN + k0 + d];
    __syncthreads();
    float a0 = 0.f, a1 = 0.f, a2 = 0.f, a3 = 0.f;
    const float* Wp = W + (size_t)k0 * D + d;
#pragma unroll 8
    for (int i = 0; i < DIN / KSLICES; i += 4) {
        a0 = fmaf(xs[i + 0], Wp[(i + 0) * D], a0);
        a1 = fmaf(xs[i + 1], Wp[(i + 1) * D], a1);
        a2 = fmaf(xs[i + 2], Wp[(i + 2) * D], a2);
        a3 = fmaf(xs[i + 3], Wp[(i + 3) * D], a3);
    }
    g_qpart[(ks * B + row) * D + d] = (a0 + a1) + (a2 + a3);
}

// ---------------- Kernel A2: reduce partials + bias + qnorm ----------------
__global__ void encoder_reduce_kernel(const float* __restrict__ bvec) {
    __shared__ float red[4];
    int row = blockIdx.x;
    int d = threadIdx.x;  // 128
    float acc = bvec[d];
#pragma unroll
    for (int ks = 0; ks < KSLICES; ks++)
        acc += g_qpart[(ks * B + row) * D + d];
    g_q[row * D + d] = acc;
    float s = acc * acc;
#pragma unroll
    for (int o = 16; o > 0; o >>= 1) s += __shfl_xor_sync(0xffffffffu, s, o);
    if ((d & 31) == 0) red[d >> 5] = s;
    __syncthreads();
    if (d == 0) g_qnorm[row] = red[0] + red[1] + red[2] + red[3];
}

// ---------------- Kernel B: fused distance + per-block top-5 ----------------
// block tile: 32 q x 256 r, thread tile 4q x 8r, 256 threads, dyn smem 147456 B
__global__ __launch_bounds__(256, 1)
void dist_topk_kernel(const float* __restrict__ reps, int N, int ntiles) {
    extern __shared__ float4 smem[];
    float4* Qs = smem;              // 32 rows x 32 chunks (16 KB), swizzled
    float4* Rs = smem + 32 * 32;    // 256 rows x 32 chunks (128 KB), swizzled
    float* RsF = (float*)Rs;

    int tid = threadIdx.x;
    int tile = blockIdx.x;
    long base = (long)tile * RTILE;

    const float4* q4 = (const float4*)g_q;
#pragma unroll
    for (int it = 0; it < 4; it++) {
        int idx = tid + it * 256;
        int r = idx >> 5, c = idx & 31;
        Qs[r * 32 + ((c + r) & 31)] = q4[r * 32 + c];
    }
    const float4* reps4 = (const float4*)reps;
#pragma unroll
    for (int it = 0; it < 32; it++) {
        int idx = tid + it * 256;
        int r = idx >> 5, c = idx & 31;
        long grow = base + r;
        float4 v = make_float4(0.f, 0.f, 0.f, 0.f);
        if (grow < (long)N) v = reps4[grow * 32 + c];
        Rs[r * 32 + ((c + r) & 31)] = v;
    }
    __syncthreads();

    int qg = tid & 7;        // 8 q-groups  -> q = qg + 8*j, j<4
    int rg = tid >> 3;       // 32 r-groups -> r = rg*8 + i, i<8

    float acc[4][8];
#pragma unroll
    for (int j = 0; j < 4; j++)
#pragma unroll
        for (int i = 0; i < 8; i++) acc[j][i] = 0.f;

#pragma unroll 2
    for (int c = 0; c < 32; c++) {
        float4 qf[4], rf[8];
#pragma unroll
        for (int j = 0; j < 4; j++) {
            int q = qg + 8 * j;
            qf[j] = Qs[q * 32 + ((c + q) & 31)];
        }
#pragma unroll
        for (int i = 0; i < 8; i++) {
            int r = rg * 8 + i;
            rf[i] = Rs[r * 32 + ((c + r) & 31)];
        }
#pragma unroll
        for (int j = 0; j < 4; j++)
#pragma unroll
            for (int i = 0; i < 8; i++) {
                acc[j][i] = fmaf(qf[j].x, rf[i].x, acc[j][i]);
                acc[j][i] = fmaf(qf[j].y, rf[i].y, acc[j][i]);
                acc[j][i] = fmaf(qf[j].z, rf[i].z, acc[j][i]);
                acc[j][i] = fmaf(qf[j].w, rf[i].w, acc[j][i]);
            }
    }
    __syncthreads();

    // rnorm per tile row (256 threads, one row each) while Rs still intact
    float rn = 0.f;
    {
#pragma unroll 8
        for (int c = 0; c < 32; c++) {
            float4 v = Rs[tid * 32 + ((c + tid) & 31)];
            rn = fmaf(v.x, v.x, fmaf(v.y, v.y, fmaf(v.z, v.z, fmaf(v.w, v.w, rn))));
        }
        if (base + tid >= (long)N) rn = 1e30f;
    }
    __syncthreads();
    // overlay scratch onto Rs: rn[0..255], dist[256 + q*256 + r]
    RsF[tid] = rn;
    __syncthreads();
    float* dist = RsF + 256;
#pragma unroll
    for (int j = 0; j < 4; j++) {
        int q = qg + 8 * j;
#pragma unroll
        for (int i = 0; i < 8; i++) {
            int r = rg * 8 + i;
            dist[q * 256 + r] = RsF[r] - 2.f * acc[j][i];  // |r|^2 - 2 q.r
        }
    }
    __syncthreads();

    // per-q top-5 over 256 rows: warp w handles queries 4w..4w+3
    int wid = tid >> 5, lane = tid & 31;
    long cstride = (long)ntiles * TOPK;
    for (int q = wid * 4; q < wid * 4 + 4; q++) {
        unsigned long long kk[8];
#pragma unroll
        for (int m = 0; m < 8; m++)
            kk[m] = pack_key(dist[q * 256 + lane + 32 * m],
                             (unsigned)(base + lane + 32 * m));
        unsigned long long* candOut = g_cand + (long)q * cstride + (long)tile * TOPK;
#pragma unroll
        for (int s = 0; s < TOPK; s++) {
            unsigned long long m = kk[0];
#pragma unroll
            for (int t = 1; t < 8; t++) m = ullmin2(m, kk[t]);
#pragma unroll
            for (int o = 16; o > 0; o >>= 1)
                m = ullmin2(m, __shfl_xor_sync(0xffffffffu, m, o));
            if (lane == 0) candOut[s] = m;
#pragma unroll
            for (int t = 0; t < 8; t++)
                if (kk[t] == m) kk[t] = ~0ull;
        }
    }
}

// ---------------- Kernel C: global merge + softmax + action gather ----------------
__global__ void final_kernel(const float* __restrict__ actions,
                             float* __restrict__ out, int ntiles) {
    __shared__ unsigned long long sh[256 * TOPK];
    __shared__ float dshare[TOPK];
    __shared__ unsigned ishare[TOPK];
    int q = blockIdx.x, tid = threadIdx.x;
    long total = (long)ntiles * TOPK;
    const unsigned long long* src = g_cand + (long)q * total;

    unsigned long long loc[TOPK];
#pragma unroll
    for (int i = 0; i < TOPK; i++) loc[i] = ~0ull;

    for (long i = tid; i < total; i += 256) {
        unsigned long long key = src[i];
        if (key < loc[TOPK - 1]) {
            loc[TOPK - 1] = key;
#pragma unroll
            for (int j = TOPK - 1; j > 0; j--) {
                if (loc[j] < loc[j - 1]) {
                    unsigned long long t = loc[j]; loc[j] = loc[j - 1]; loc[j - 1] = t;
                }
            }
        }
    }
#pragma unroll
    for (int i = 0; i < TOPK; i++) sh[tid * TOPK + i] = loc[i];
    __syncthreads();

    for (int stride = 128; stride >= 1; stride >>= 1) {
        if (tid < stride) {
            unsigned long long a[TOPK], b[TOPK], res[TOPK];
#pragma unroll
            for (int i = 0; i < TOPK; i++) { a[i] = sh[tid * TOPK + i]; b[i] = sh[(tid + stride) * TOPK + i]; }
            int ia = 0, ib = 0;
#pragma unroll
            for (int i = 0; i < TOPK; i++) {
                if (a[ia] <= b[ib]) res[i] = a[ia++];
                else res[i] = b[ib++];
            }
#pragma unroll
            for (int i = 0; i < TOPK; i++) sh[tid * TOPK + i] = res[i];
        }
        __syncthreads();
    }

    if (tid < TOPK) {
        unsigned long long key = sh[tid];
        float v = unpack_val(key);
        float sq = g_qnorm[q] + v;
        dshare[tid] = sqrtf(fmaxf(sq, 1e-12f));
        ishare[tid] = (unsigned)(key & 0xffffffffull);
    }
    __syncthreads();

    if (tid < A_DIM) {
        float mx = -1e30f;
#pragma unroll
        for (int i = 0; i < TOPK; i++) mx = fmaxf(mx, -dshare[i]);
        float w[TOPK], sum = 0.f;
#pragma unroll
        for (int i = 0; i < TOPK; i++) { w[i] = expf(-dshare[i] - mx); sum += w[i]; }
        float o = 0.f;
#pragma unroll
        for (int i = 0; i < TOPK; i++)
            o += (w[i] / sum) * actions[(long)ishare[i] * A_DIM + tid];
        out[q * A_DIM + tid] = o;
    }
}

extern "C" void kernel_launch(void* const* d_in, const int* in_sizes, int n_in,
                              void* d_out, int out_size) {
    const float* x       = (const float*)d_in[0];
    const float* W_enc   = (const float*)d_in[1];
    const float* b_enc   = (const float*)d_in[2];
    const float* reps    = (const float*)d_in[3];
    const float* actions = (const float*)d_in[4];

    int N = in_sizes[3] / D;
    int ntiles = (N + RTILE - 1) / RTILE;

    const int smem_bytes = (32 * 32 + 256 * 32) * 16;  // 147456
    cudaFuncSetAttribute(dist_topk_kernel,
                         cudaFuncAttributeMaxDynamicSharedMemorySize, smem_bytes);

    encoder_part_kernel<<<dim3(B, KSLICES), 128>>>(x, W_enc);
    encoder_reduce_kernel<<<B, 128>>>(b_enc);
    dist_topk_kernel<<<ntiles, 256, smem_bytes>>>(reps, N, ntiles);
    final_kernel<<<B, 256>>>(actions, (float*)d_out, ntiles);
}

// round 7
// speedup vs baseline: 2.2842x; 1.2210x over previous
#include <cuda_runtime.h>
#include <cstdint>

#define B 32
#define D 128
#define DIN 2048
#define A_DIM 7
#define TOPK 5
#define KSLICES 16
#define GRID 148
#define KEEP 8
#define CAND 16

// ---- dynamic smem layout for dist kernel ----
#define SM_STAGE0 0
#define SM_STAGE1 65536
#define SM_QBF    131072   // 32x128 bf16, row stride 256B, 16B-chunk XOR swizzle (8192 B)
#define SM_ABF    139264   // 128x128 bf16, same layout (32768 B)
#define SM_DIST   172032   // 128 x 34 floats (17408 B)
#define SM_RN     189440   // 128 floats
#define SM_KEYS   189952   // 32 q x KEEP u64 (2048 B)
#define SM_TOTAL  192000

__device__ __align__(16) float g_q[B * D];
__device__ __align__(16) float g_qpart[KSLICES * B * D];
__device__ float g_qnorm[B];
__device__ unsigned long long g_cand[(size_t)B * GRID * KEEP];

__device__ __forceinline__ uint32_t smem_u32(const void* p) {
    uint32_t a;
    asm("{ .reg .u64 t; cvta.to.shared.u64 t, %1; cvt.u32.u64 %0, t; }" : "=r"(a) : "l"(p));
    return a;
}
__device__ __forceinline__ unsigned long long pack_key(float v, unsigned idx) {
    unsigned u = __float_as_uint(v);
    u = (u & 0x80000000u) ? ~u : (u | 0x80000000u);
    return ((unsigned long long)u << 32) | (unsigned long long)idx;
}
__device__ __forceinline__ float unpack_val(unsigned long long key) {
    unsigned u = (unsigned)(key >> 32);
    u = (u & 0x80000000u) ? (u & 0x7fffffffu) : ~u;
    return __uint_as_float(u);
}

#define CP_ASYNC16(dst, src) \
    asm volatile("cp.async.cg.shared.global [%0], [%1], 16;" :: "r"(dst), "l"(src) : "memory")
#define CP_COMMIT() asm volatile("cp.async.commit_group;" ::: "memory")
#define CP_WAIT1()  asm volatile("cp.async.wait_group 1;" ::: "memory")

#define LDMX4(r0_, r1_, r2_, r3_, a_) \
    asm volatile("ldmatrix.sync.aligned.m8n8.x4.shared.b16 {%0,%1,%2,%3}, [%4];" \
        : "=r"(r0_), "=r"(r1_), "=r"(r2_), "=r"(r3_) : "r"(a_))

#define MMA16816(c_, a_, b_) \
    asm volatile("mma.sync.aligned.m16n8k16.row.col.f32.bf16.bf16.f32 " \
        "{%0,%1,%2,%3}, {%4,%5,%6,%7}, {%8,%9}, {%0,%1,%2,%3};" \
        : "+f"((c_)[0]), "+f"((c_)[1]), "+f"((c_)[2]), "+f"((c_)[3]) \
        : "r"((a_)[0]), "r"((a_)[1]), "r"((a_)[2]), "r"((a_)[3]), \
          "r"((b_)[0]), "r"((b_)[1]))

// ---------------- encoder (split-K) ----------------
__global__ void encoder_part_kernel(const float* __restrict__ x,
                                    const float* __restrict__ W) {
    __shared__ float xs[DIN / KSLICES];
    int row = blockIdx.x, ks = blockIdx.y, d = threadIdx.x;
    int k0 = ks * (DIN / KSLICES);
    xs[d] = x[row * DIN + k0 + d];
    __syncthreads();
    float a0 = 0.f, a1 = 0.f, a2 = 0.f, a3 = 0.f;
    const float* Wp = W + (size_t)k0 * D + d;
#pragma unroll 8
    for (int i = 0; i < DIN / KSLICES; i += 4) {
        a0 = fmaf(xs[i + 0], Wp[(i + 0) * D], a0);
        a1 = fmaf(xs[i + 1], Wp[(i + 1) * D], a1);
        a2 = fmaf(xs[i + 2], Wp[(i + 2) * D], a2);
        a3 = fmaf(xs[i + 3], Wp[(i + 3) * D], a3);
    }
    g_qpart[(ks * B + row) * D + d] = (a0 + a1) + (a2 + a3);
}

__global__ void encoder_reduce_kernel(const float* __restrict__ bvec) {
    __shared__ float red[4];
    int row = blockIdx.x, d = threadIdx.x;
    float acc = bvec[d];
#pragma unroll
    for (int ks = 0; ks < KSLICES; ks++) acc += g_qpart[(ks * B + row) * D + d];
    g_q[row * D + d] = acc;
    float s = acc * acc;
#pragma unroll
    for (int o = 16; o > 0; o >>= 1) s += __shfl_xor_sync(0xffffffffu, s, o);
    if ((d & 31) == 0) red[d >> 5] = s;
    __syncthreads();
    if (d == 0) g_qnorm[row] = red[0] + red[1] + red[2] + red[3];
}

// ---------------- dist: persistent HMMA bf16 + approx top-8 ----------------
__global__ __launch_bounds__(256, 1)
void dist_topk_kernel(const float* __restrict__ reps, int N, int ntiles) {
    extern __shared__ __align__(128) char smem[];
    uint32_t sb = smem_u32(smem);
    int tid = threadIdx.x, lane = tid & 31, wid = tid >> 5;
    int bid = blockIdx.x;

    unsigned long long* keys = (unsigned long long*)(smem + SM_KEYS);
    float* rn_s = (float*)(smem + SM_RN);
    float* dist = (float*)(smem + SM_DIST);

    for (int i = tid; i < 32 * KEEP; i += 256) keys[i] = ~0ull;

    // convert Q (g_q fp32, 32x128) -> QBF bf16 (row stride 256B, chunk swizzle)
#pragma unroll
    for (int it = 0; it < 2; it++) {
        int idx = tid + it * 256;   // 512 chunks
        int row = idx >> 4, c = idx & 15;
        float4 v0 = ((const float4*)g_q)[row * 32 + c * 2];
        float4 v1 = ((const float4*)g_q)[row * 32 + c * 2 + 1];
        uint32_t p0, p1, p2, p3;
        asm("cvt.rn.bf16x2.f32 %0, %1, %2;" : "=r"(p0) : "f"(v0.y), "f"(v0.x));
        asm("cvt.rn.bf16x2.f32 %0, %1, %2;" : "=r"(p1) : "f"(v0.w), "f"(v0.z));
        asm("cvt.rn.bf16x2.f32 %0, %1, %2;" : "=r"(p2) : "f"(v1.y), "f"(v1.x));
        asm("cvt.rn.bf16x2.f32 %0, %1, %2;" : "=r"(p3) : "f"(v1.w), "f"(v1.z));
        uint32_t off = (uint32_t)(row * 256 + ((c ^ (row & 7)) << 4));
        asm volatile("st.shared.v4.b32 [%0], {%1,%2,%3,%4};"
                     :: "r"(sb + SM_QBF + off), "r"(p0), "r"(p1), "r"(p2), "r"(p3) : "memory");
    }

    // prologue: stage tile bid into stage0
    {
        int t = bid;
        if (t < ntiles) {
            int rows = N - t * 128; if (rows > 128) rows = 128;
            const char* src = (const char*)(reps + (size_t)t * 16384);
#pragma unroll
            for (int it = 0; it < 16; it++) {
                int idx = tid + it * 256;          // 4096 chunks of 16B
                int row = idx >> 5;
                if (row < rows) CP_ASYNC16(sb + SM_STAGE0 + idx * 16, src + idx * 16);
            }
        }
        CP_COMMIT();
    }

    int li = 0;
    for (int t = bid; t < ntiles; t += GRID, li++) {
        // prefetch next tile into other stage
        int tn = t + GRID;
        if (tn < ntiles) {
            int rows = N - tn * 128; if (rows > 128) rows = 128;
            uint32_t dstb = sb + (((li + 1) & 1) ? SM_STAGE1 : SM_STAGE0);
            const char* src = (const char*)(reps + (size_t)tn * 16384);
#pragma unroll
            for (int it = 0; it < 16; it++) {
                int idx = tid + it * 256;
                int row = idx >> 5;
                if (row < rows) CP_ASYNC16(dstb + idx * 16, src + idx * 16);
            }
        }
        CP_COMMIT();
        CP_WAIT1();
        __syncthreads();

        const float4* stg = (const float4*)(smem + ((li & 1) ? SM_STAGE1 : SM_STAGE0));
        long base = (long)t * 128;
        int rows = N - t * 128; if (rows > 128) rows = 128;

        // convert fp32 -> ABF bf16 + row norms
#pragma unroll
        for (int it = 0; it < 8; it++) {
            int idx = tid + it * 256;   // 2048 chunks
            int row = idx >> 4, c = idx & 15;
            float4 v0 = stg[row * 32 + c * 2];
            float4 v1 = stg[row * 32 + c * 2 + 1];
            float p = fmaf(v0.x, v0.x, fmaf(v0.y, v0.y, fmaf(v0.z, v0.z, v0.w * v0.w)));
            p = fmaf(v1.x, v1.x, fmaf(v1.y, v1.y, fmaf(v1.z, v1.z, fmaf(v1.w, v1.w, p))));
#pragma unroll
            for (int o = 8; o > 0; o >>= 1) p += __shfl_xor_sync(0xffffffffu, p, o);
            if ((tid & 15) == 0) rn_s[row] = (row < rows) ? p : __int_as_float(0x7f800000);
            uint32_t p0, p1, p2, p3;
            asm("cvt.rn.bf16x2.f32 %0, %1, %2;" : "=r"(p0) : "f"(v0.y), "f"(v0.x));
            asm("cvt.rn.bf16x2.f32 %0, %1, %2;" : "=r"(p1) : "f"(v0.w), "f"(v0.z));
            asm("cvt.rn.bf16x2.f32 %0, %1, %2;" : "=r"(p2) : "f"(v1.y), "f"(v1.x));
            asm("cvt.rn.bf16x2.f32 %0, %1, %2;" : "=r"(p3) : "f"(v1.w), "f"(v1.z));
            uint32_t off = (uint32_t)(row * 256 + ((c ^ (row & 7)) << 4));
            asm volatile("st.shared.v4.b32 [%0], {%1,%2,%3,%4};"
                         :: "r"(sb + SM_ABF + off), "r"(p0), "r"(p1), "r"(p2), "r"(p3) : "memory");
        }
        __syncthreads();

        // MMA: warp w -> reps rows 16w..16w+15, all 32 q, K=128
        {
            int r0 = wid * 16;
            float c0[4], c1[4], c2[4], c3[4];
#pragma unroll
            for (int i = 0; i < 4; i++) { c0[i] = 0.f; c1[i] = 0.f; c2[i] = 0.f; c3[i] = 0.f; }
            int g = lane >> 3, rr = lane & 7;
            int arow = r0 + rr + (g & 1) * 8;
            int achunkoff = g >> 1;
            int bchunkoff = g & 1;
#pragma unroll
            for (int k = 0; k < 8; k++) {
                uint32_t a[4], b01[4], b23[4];
                {
                    int chunk = k * 2 + achunkoff;
                    uint32_t addr = sb + SM_ABF + (uint32_t)(arow * 256 + ((chunk ^ (arow & 7)) << 4));
                    LDMX4(a[0], a[1], a[2], a[3], addr);
                }
                {
                    int qrow = (g >> 1) * 8 + rr;
                    int chunk = k * 2 + bchunkoff;
                    uint32_t addr = sb + SM_QBF + (uint32_t)(qrow * 256 + ((chunk ^ (qrow & 7)) << 4));
                    LDMX4(b01[0], b01[1], b01[2], b01[3], addr);
                }
                {
                    int qrow = 16 + (g >> 1) * 8 + rr;
                    int chunk = k * 2 + bchunkoff;
                    uint32_t addr = sb + SM_QBF + (uint32_t)(qrow * 256 + ((chunk ^ (qrow & 7)) << 4));
                    LDMX4(b23[0], b23[1], b23[2], b23[3], addr);
                }
                MMA16816(c0, a, b01);
                MMA16816(c1, a, (b01 + 2));
                MMA16816(c2, a, b23);
                MMA16816(c3, a, (b23 + 2));
            }
            int rowa = r0 + (lane >> 2);
            int rowb = rowa + 8;
            int colb = 2 * (lane & 3);
            float* cc[4] = {c0, c1, c2, c3};
#pragma unroll
            for (int nt = 0; nt < 4; nt++) {
                int col = nt * 8 + colb;
                asm volatile("st.shared.v2.f32 [%0], {%1,%2};"
                             :: "r"(sb + SM_DIST + (uint32_t)((rowa * 34 + col) * 4)),
                                "f"(cc[nt][0]), "f"(cc[nt][1]) : "memory");
                asm volatile("st.shared.v2.f32 [%0], {%1,%2};"
                             :: "r"(sb + SM_DIST + (uint32_t)((rowb * 34 + col) * 4)),
                                "f"(cc[nt][2]), "f"(cc[nt][3]) : "memory");
            }
        }
        __syncthreads();

        // filter: warp w owns queries 4w..4w+3 exclusively
#pragma unroll
        for (int qi = 0; qi < 4; qi++) {
            int q = wid * 4 + qi;
            unsigned long long* L = &keys[q * KEEP];
#pragma unroll
            for (int m = 0; m < 4; m++) {
                int r = lane + 32 * m;
                float dv = dist[r * 34 + q];
                float v = fmaf(-2.f, dv, rn_s[r]);
                unsigned long long key = pack_key(v, (unsigned)(base + r));
                unsigned long long thr = L[KEEP - 1];
                unsigned mask = __ballot_sync(0xffffffffu, key < thr);
                while (mask) {
                    int ld = __ffs(mask) - 1;
                    if (lane == ld) {
                        if (key < L[KEEP - 1]) {
                            L[KEEP - 1] = key;
#pragma unroll
                            for (int j = KEEP - 1; j > 0; j--) {
                                if (L[j] < L[j - 1]) {
                                    unsigned long long tt = L[j]; L[j] = L[j - 1]; L[j - 1] = tt;
                                }
                            }
                        }
                    }
                    __syncwarp();
                    mask &= mask - 1;
                }
            }
        }
        __syncthreads();
    }

    // write per-block candidates (keys already sorted per q)
    if (tid < 32 * KEEP) {
        int q = tid >> 3, s = tid & 7;
        g_cand[(size_t)q * (GRID * KEEP) + (size_t)bid * KEEP + s] = keys[q * KEEP + s];
    }
}

// ---------------- final: merge approx, exact re-rank, softmax, gather ----------------
__global__ void final_kernel(const float* __restrict__ reps,
                             const float* __restrict__ actions,
                             float* __restrict__ out) {
    __shared__ unsigned long long sh[128 * CAND];
    __shared__ unsigned long long exactk[CAND];
    __shared__ float wsh[TOPK];
    __shared__ unsigned ish[TOPK];
    int q = blockIdx.x, tid = threadIdx.x;
    const int total = GRID * KEEP;
    const unsigned long long* src = g_cand + (size_t)q * total;

    unsigned long long loc[CAND];
#pragma unroll
    for (int i = 0; i < CAND; i++) loc[i] = ~0ull;
    for (int i = tid; i < total; i += 128) {
        unsigned long long key = src[i];
        if (key < loc[CAND - 1]) {
            loc[CAND - 1] = key;
#pragma unroll
            for (int j = CAND - 1; j > 0; j--) {
                if (loc[j] < loc[j - 1]) {
                    unsigned long long tt = loc[j]; loc[j] = loc[j - 1]; loc[j - 1] = tt;
                }
            }
        }
    }
#pragma unroll
    for (int i = 0; i < CAND; i++) sh[tid * CAND + i] = loc[i];
    __syncthreads();

    for (int stride = 64; stride >= 1; stride >>= 1) {
        if (tid < stride) {
            unsigned long long a[CAND], b[CAND], r[CAND];
#pragma unroll
            for (int i = 0; i < CAND; i++) { a[i] = sh[tid * CAND + i]; b[i] = sh[(tid + stride) * CAND + i]; }
            int ia = 0, ib = 0;
#pragma unroll
            for (int i = 0; i < CAND; i++) {
                if (a[ia] <= b[ib]) r[i] = a[ia++];
                else r[i] = b[ib++];
            }
#pragma unroll
            for (int i = 0; i < CAND; i++) sh[tid * CAND + i] = r[i];
        }
        __syncthreads();
    }

    // exact re-rank of top-CAND
    if (tid < CAND) {
        unsigned long long key = sh[tid];
        unsigned idx = (unsigned)(key & 0xffffffffull);
        float dx;
        if (key == ~0ull) {
            dx = __int_as_float(0x7f800000); idx = 0;
        } else {
            const float4* qv = (const float4*)(g_q + q * D);
            const float4* rv = (const float4*)(reps + (size_t)idx * D);
            float dot = 0.f, rn2 = 0.f;
#pragma unroll 8
            for (int c = 0; c < 32; c++) {
                float4 a = qv[c], b = rv[c];
                dot = fmaf(a.x, b.x, fmaf(a.y, b.y, fmaf(a.z, b.z, fmaf(a.w, b.w, dot))));
                rn2 = fmaf(b.x, b.x, fmaf(b.y, b.y, fmaf(b.z, b.z, fmaf(b.w, b.w, rn2))));
            }
            float sq = g_qnorm[q] + rn2 - 2.f * dot;
            dx = sqrtf(fmaxf(sq, 1e-12f));
        }
        exactk[tid] = pack_key(dx, idx);
    }
    __syncthreads();

    if (tid == 0) {
        for (int i = 1; i < CAND; i++) {
            unsigned long long k = exactk[i];
            int j = i - 1;
            while (j >= 0 && exactk[j] > k) { exactk[j + 1] = exactk[j]; j--; }
            exactk[j + 1] = k;
        }
        float mx = -unpack_val(exactk[0]);
        float sum = 0.f;
#pragma unroll
        for (int s = 0; s < TOPK; s++) {
            float ds = unpack_val(exactk[s]);
            float w = expf(-ds - mx);
            wsh[s] = w; sum += w;
            ish[s] = (unsigned)(exactk[s] & 0xffffffffull);
        }
#pragma unroll
        for (int s = 0; s < TOPK; s++) wsh[s] /= sum;
    }
    __syncthreads();

    if (tid < A_DIM) {
        float o = 0.f;
#pragma unroll
        for (int s = 0; s < TOPK; s++)
            o += wsh[s] * actions[(size_t)ish[s] * A_DIM + tid];
        out[q * A_DIM + tid] = o;
    }
}

extern "C" void kernel_launch(void* const* d_in, const int* in_sizes, int n_in,
                              void* d_out, int out_size) {
    const float* x       = (const float*)d_in[0];
    const float* W_enc   = (const float*)d_in[1];
    const float* b_enc   = (const float*)d_in[2];
    const float* reps    = (const float*)d_in[3];
    const float* actions = (const float*)d_in[4];

    int N = in_sizes[3] / D;
    int ntiles = (N + 127) / 128;

    cudaFuncSetAttribute(dist_topk_kernel,
                         cudaFuncAttributeMaxDynamicSharedMemorySize, SM_TOTAL);

    encoder_part_kernel<<<dim3(B, KSLICES), 128>>>(x, W_enc);
    encoder_reduce_kernel<<<B, 128>>>(b_enc);
    dist_topk_kernel<<<GRID, 256, SM_TOTAL>>>(reps, N, ntiles);
    final_kernel<<<B, 128>>>(reps, actions, (float*)d_out);
}

// round 16
// speedup vs baseline: 2.4571x; 1.0757x over previous
#include <cuda_runtime.h>
#include <cstdint>

#define B 32
#define D 128
#define DIN 2048
#define A_DIM 7
#define TOPK 5
#define KSLICES 16
#define GRID 148
#define KEEP 8
#define CAND 16
#define NCAND (GRID * KEEP)   // 1184

// ---- dynamic smem layout for dist kernel ----
#define SM_STAGE0 0
#define SM_STAGE1 65536
#define SM_QBF    131072   // 32x128 bf16, row stride 256B, 16B-chunk XOR swizzle (8192 B)
#define SM_ABF    139264   // 128x128 bf16, same layout (32768 B)
#define SM_DIST   172032   // 128 x 34 floats (17408 B)
#define SM_RN     189440   // 128 floats
#define SM_KEYS   189952   // 32 q x KEEP u64 (2048 B)
#define SM_FULL0  192000
#define SM_FULL1  192008
#define SM_TOTAL  192128

__device__ __align__(16) float g_q[B * D];
__device__ __align__(16) float g_qpart[KSLICES * B * D];
__device__ float g_qnorm[B];
__device__ unsigned long long g_cand[(size_t)B * NCAND];

__device__ __forceinline__ uint32_t smem_u32(const void* p) {
    uint32_t a;
    asm("{ .reg .u64 t; cvta.to.shared.u64 t, %1; cvt.u32.u64 %0, t; }" : "=r"(a) : "l"(p));
    return a;
}
__device__ __forceinline__ unsigned long long pack_key(float v, unsigned idx) {
    unsigned u = __float_as_uint(v);
    u = (u & 0x80000000u) ? ~u : (u | 0x80000000u);
    return ((unsigned long long)u << 32) | (unsigned long long)idx;
}
__device__ __forceinline__ float unpack_val(unsigned long long key) {
    unsigned u = (unsigned)(key >> 32);
    u = (u & 0x80000000u) ? (u & 0x7fffffffu) : ~u;
    return __uint_as_float(u);
}
__device__ __forceinline__ unsigned long long ullmin2(unsigned long long a, unsigned long long b) {
    return a < b ? a : b;
}

#define MBAR_INIT(a, c) asm volatile("mbarrier.init.shared.b64 [%0], %1;" :: "r"(a), "r"(c) : "memory")
#define MBAR_EXPECT_TX(a, b) asm volatile("mbarrier.arrive.expect_tx.shared.b64 _, [%0], %1;" :: "r"(a), "r"(b) : "memory")
#define MBAR_WAIT(a, ph) do { \
    uint32_t _m = (a), _p = (ph), _done; \
    asm volatile("{\n\t.reg .pred p;\n\tmbarrier.try_wait.parity.acquire.cta.shared::cta.b64 p, [%1], %2;\n\tselp.b32 %0, 1, 0, p;\n\t}" \
        : "=r"(_done) : "r"(_m), "r"(_p) : "memory"); \
    if (!_done) { \
        asm volatile("{\n\t.reg .pred P1;\n\tWL_%=:\n\tmbarrier.try_wait.parity.acquire.cta.shared::cta.b64 P1, [%0], %1, 0x989680;\n\t@P1 bra.uni WD_%=;\n\tbra.uni WL_%=;\n\tWD_%=:\n\t}" \
            :: "r"(_m), "r"(_p) : "memory"); \
    } } while (0)
#define BULK_CP(dst, src, bytes, mbar) \
    asm volatile("cp.async.bulk.shared::cluster.global.mbarrier::complete_tx::bytes [%0], [%1], %2, [%3];" \
        :: "r"(dst), "l"(src), "r"(bytes), "r"(mbar) : "memory")

#define LDMX4(r0_, r1_, r2_, r3_, a_) \
    asm volatile("ldmatrix.sync.aligned.m8n8.x4.shared.b16 {%0,%1,%2,%3}, [%4];" \
        : "=r"(r0_), "=r"(r1_), "=r"(r2_), "=r"(r3_) : "r"(a_))

#define MMA16816(c_, a_, b_) \
    asm volatile("mma.sync.aligned.m16n8k16.row.col.f32.bf16.bf16.f32 " \
        "{%0,%1,%2,%3}, {%4,%5,%6,%7}, {%8,%9}, {%0,%1,%2,%3};" \
        : "+f"((c_)[0]), "+f"((c_)[1]), "+f"((c_)[2]), "+f"((c_)[3]) \
        : "r"((a_)[0]), "r"((a_)[1]), "r"((a_)[2]), "r"((a_)[3]), \
          "r"((b_)[0]), "r"((b_)[1]))

// ---------------- encoder (split-K) ----------------
__global__ void encoder_part_kernel(const float* __restrict__ x,
                                    const float* __restrict__ W) {
    __shared__ float xs[DIN / KSLICES];
    int row = blockIdx.x, ks = blockIdx.y, d = threadIdx.x;
    int k0 = ks * (DIN / KSLICES);
    xs[d] = x[row * DIN + k0 + d];
    __syncthreads();
    float a0 = 0.f, a1 = 0.f, a2 = 0.f, a3 = 0.f;
    const float* Wp = W + (size_t)k0 * D + d;
#pragma unroll 8
    for (int i = 0; i < DIN / KSLICES; i += 4) {
        a0 = fmaf(xs[i + 0], Wp[(i + 0) * D], a0);
        a1 = fmaf(xs[i + 1], Wp[(i + 1) * D], a1);
        a2 = fmaf(xs[i + 2], Wp[(i + 2) * D], a2);
        a3 = fmaf(xs[i + 3], Wp[(i + 3) * D], a3);
    }
    g_qpart[(ks * B + row) * D + d] = (a0 + a1) + (a2 + a3);
}

__global__ void encoder_reduce_kernel(const float* __restrict__ bvec) {
    __shared__ float red[4];
    int row = blockIdx.x, d = threadIdx.x;
    float acc = bvec[d];
#pragma unroll
    for (int ks = 0; ks < KSLICES; ks++) acc += g_qpart[(ks * B + row) * D + d];
    g_q[row * D + d] = acc;
    float s = acc * acc;
#pragma unroll
    for (int o = 16; o > 0; o >>= 1) s += __shfl_xor_sync(0xffffffffu, s, o);
    if ((d & 31) == 0) red[d >> 5] = s;
    __syncthreads();
    if (d == 0) g_qnorm[row] = red[0] + red[1] + red[2] + red[3];
}

// ---------------- dist: persistent HMMA bf16 + bulk-async staging ----------------
__global__ __launch_bounds__(256, 1)
void dist_topk_kernel(const float* __restrict__ reps, int N, int ntiles) {
    extern __shared__ __align__(128) char smem[];
    uint32_t sb = smem_u32(smem);
    int tid = threadIdx.x, lane = tid & 31, wid = tid >> 5;
    int bid = blockIdx.x;

    unsigned long long* keys = (unsigned long long*)(smem + SM_KEYS);
    float* rn_s = (float*)(smem + SM_RN);
    float* dist = (float*)(smem + SM_DIST);

    for (int i = tid; i < 32 * KEEP; i += 256) keys[i] = ~0ull;

    if (tid == 0) {
        MBAR_INIT(sb + SM_FULL0, 1);
        MBAR_INIT(sb + SM_FULL1, 1);
    }

    // convert Q (g_q fp32, 32x128) -> QBF bf16 (row stride 256B, chunk swizzle)
#pragma unroll
    for (int it = 0; it < 2; it++) {
        int idx = tid + it * 256;   // 512 chunks
        int row = idx >> 4, c = idx & 15;
        float4 v0 = ((const float4*)g_q)[row * 32 + c * 2];
        float4 v1 = ((const float4*)g_q)[row * 32 + c * 2 + 1];
        uint32_t p0, p1, p2, p3;
        asm("cvt.rn.bf16x2.f32 %0, %1, %2;" : "=r"(p0) : "f"(v0.y), "f"(v0.x));
        asm("cvt.rn.bf16x2.f32 %0, %1, %2;" : "=r"(p1) : "f"(v0.w), "f"(v0.z));
        asm("cvt.rn.bf16x2.f32 %0, %1, %2;" : "=r"(p2) : "f"(v1.y), "f"(v1.x));
        asm("cvt.rn.bf16x2.f32 %0, %1, %2;" : "=r"(p3) : "f"(v1.w), "f"(v1.z));
        uint32_t off = (uint32_t)(row * 256 + ((c ^ (row & 7)) << 4));
        asm volatile("st.shared.v4.b32 [%0], {%1,%2,%3,%4};"
                     :: "r"(sb + SM_QBF + off), "r"(p0), "r"(p1), "r"(p2), "r"(p3) : "memory");
    }
    __syncthreads();   // mbarrier init visible to all before any arrive/wait

    // prologue: bulk copy tile bid into stage0
    if (tid == 0 && bid < ntiles) {
        int rows = N - bid * 128; if (rows > 128) rows = 128;
        uint32_t bytes = (uint32_t)rows * 512u;
        MBAR_EXPECT_TX(sb + SM_FULL0, bytes);
        BULK_CP(sb + SM_STAGE0, reps + (size_t)bid * 16384, bytes, sb + SM_FULL0);
    }

    int li = 0;
    for (int t = bid; t < ntiles; t += GRID, li++) {
        // prefetch next tile into the other stage buffer
        int tn = t + GRID;
        if (tid == 0 && tn < ntiles) {
            int rows2 = N - tn * 128; if (rows2 > 128) rows2 = 128;
            uint32_t bytes = (uint32_t)rows2 * 512u;
            uint32_t mb = sb + (((li + 1) & 1) ? SM_FULL1 : SM_FULL0);
            MBAR_EXPECT_TX(mb, bytes);
            BULK_CP((uint32_t)(sb + (((li + 1) & 1) ? SM_STAGE1 : SM_STAGE0)),
                    reps + (size_t)tn * 16384, bytes, mb);
        }
        MBAR_WAIT(sb + ((li & 1) ? SM_FULL1 : SM_FULL0), (li >> 1) & 1);

        const float4* stg = (const float4*)(smem + ((li & 1) ? SM_STAGE1 : SM_STAGE0));
        long base = (long)t * 128;
        int rows = N - t * 128; if (rows > 128) rows = 128;

        // convert fp32 -> ABF bf16 + row norms
#pragma unroll
        for (int it = 0; it < 8; it++) {
            int idx = tid + it * 256;   // 2048 chunks
            int row = idx >> 4, c = idx & 15;
            float4 v0 = stg[row * 32 + c * 2];
            float4 v1 = stg[row * 32 + c * 2 + 1];
            float p = fmaf(v0.x, v0.x, fmaf(v0.y, v0.y, fmaf(v0.z, v0.z, v0.w * v0.w)));
            p = fmaf(v1.x, v1.x, fmaf(v1.y, v1.y, fmaf(v1.z, v1.z, fmaf(v1.w, v1.w, p))));
#pragma unroll
            for (int o = 8; o > 0; o >>= 1) p += __shfl_xor_sync(0xffffffffu, p, o);
            if ((tid & 15) == 0) rn_s[row] = (row < rows) ? p : __int_as_float(0x7f800000);
            uint32_t p0, p1, p2, p3;
            asm("cvt.rn.bf16x2.f32 %0, %1, %2;" : "=r"(p0) : "f"(v0.y), "f"(v0.x));
            asm("cvt.rn.bf16x2.f32 %0, %1, %2;" : "=r"(p1) : "f"(v0.w), "f"(v0.z));
            asm("cvt.rn.bf16x2.f32 %0, %1, %2;" : "=r"(p2) : "f"(v1.y), "f"(v1.x));
            asm("cvt.rn.bf16x2.f32 %0, %1, %2;" : "=r"(p3) : "f"(v1.w), "f"(v1.z));
            uint32_t off = (uint32_t)(row * 256 + ((c ^ (row & 7)) << 4));
            asm volatile("st.shared.v4.b32 [%0], {%1,%2,%3,%4};"
                         :: "r"(sb + SM_ABF + off), "r"(p0), "r"(p1), "r"(p2), "r"(p3) : "memory");
        }
        __syncthreads();

        // MMA: warp w -> reps rows 16w..16w+15, all 32 q, K=128
        {
            int r0 = wid * 16;
            float c0[4], c1[4], c2[4], c3[4];
#pragma unroll
            for (int i = 0; i < 4; i++) { c0[i] = 0.f; c1[i] = 0.f; c2[i] = 0.f; c3[i] = 0.f; }
            int g = lane >> 3, rr = lane & 7;
            int arow = r0 + rr + (g & 1) * 8;
            int achunkoff = g >> 1;
            int bchunkoff = g & 1;
#pragma unroll
            for (int k = 0; k < 8; k++) {
                uint32_t a[4], b01[4], b23[4];
                {
                    int chunk = k * 2 + achunkoff;
                    uint32_t addr = sb + SM_ABF + (uint32_t)(arow * 256 + ((chunk ^ (arow & 7)) << 4));
                    LDMX4(a[0], a[1], a[2], a[3], addr);
                }
                {
                    int qrow = (g >> 1) * 8 + rr;
                    int chunk = k * 2 + bchunkoff;
                    uint32_t addr = sb + SM_QBF + (uint32_t)(qrow * 256 + ((chunk ^ (qrow & 7)) << 4));
                    LDMX4(b01[0], b01[1], b01[2], b01[3], addr);
                }
                {
                    int qrow = 16 + (g >> 1) * 8 + rr;
                    int chunk = k * 2 + bchunkoff;
                    uint32_t addr = sb + SM_QBF + (uint32_t)(qrow * 256 + ((chunk ^ (qrow & 7)) << 4));
                    LDMX4(b23[0], b23[1], b23[2], b23[3], addr);
                }
                MMA16816(c0, a, b01);
                MMA16816(c1, a, (b01 + 2));
                MMA16816(c2, a, b23);
                MMA16816(c3, a, (b23 + 2));
            }
            int rowa = r0 + (lane >> 2);
            int rowb = rowa + 8;
            int colb = 2 * (lane & 3);
            float* cc[4] = {c0, c1, c2, c3};
#pragma unroll
            for (int nt = 0; nt < 4; nt++) {
                int col = nt * 8 + colb;
                asm volatile("st.shared.v2.f32 [%0], {%1,%2};"
                             :: "r"(sb + SM_DIST + (uint32_t)((rowa * 34 + col) * 4)),
                                "f"(cc[nt][0]), "f"(cc[nt][1]) : "memory");
                asm volatile("st.shared.v2.f32 [%0], {%1,%2};"
                             :: "r"(sb + SM_DIST + (uint32_t)((rowb * 34 + col) * 4)),
                                "f"(cc[nt][2]), "f"(cc[nt][3]) : "memory");
            }
        }
        __syncthreads();

        // filter: warp w owns queries 4w..4w+3 exclusively
#pragma unroll
        for (int qi = 0; qi < 4; qi++) {
            int q = wid * 4 + qi;
            unsigned long long* L = &keys[q * KEEP];
#pragma unroll
            for (int m = 0; m < 4; m++) {
                int r = lane + 32 * m;
                float dv = dist[r * 34 + q];
                float v = fmaf(-2.f, dv, rn_s[r]);
                unsigned long long key = pack_key(v, (unsigned)(base + r));
                unsigned long long thr = L[KEEP - 1];
                unsigned mask = __ballot_sync(0xffffffffu, key < thr);
                while (mask) {
                    int ld = __ffs(mask) - 1;
                    if (lane == ld) {
                        if (key < L[KEEP - 1]) {
                            L[KEEP - 1] = key;
#pragma unroll
                            for (int j = KEEP - 1; j > 0; j--) {
                                if (L[j] < L[j - 1]) {
                                    unsigned long long tt = L[j]; L[j] = L[j - 1]; L[j - 1] = tt;
                                }
                            }
                        }
                    }
                    __syncwarp();
                    mask &= mask - 1;
                }
            }
        }
        __syncthreads();
    }

    // write per-block candidates (keys already sorted per q)
    if (tid < 32 * KEEP) {
        int q = tid >> 3, s = tid & 7;
        g_cand[(size_t)q * NCAND + (size_t)bid * KEEP + s] = keys[q * KEEP + s];
    }
}

// ---------------- final: register-only merge + exact re-rank + softmax ----------------
__global__ void final_kernel(const float* __restrict__ reps,
                             const float* __restrict__ actions,
                             float* __restrict__ out) {
    __shared__ unsigned long long wtop[4 * CAND];
    __shared__ unsigned long long cand16[CAND];
    __shared__ unsigned long long exactk[CAND];
    __shared__ float wsh[TOPK];
    __shared__ unsigned ish[TOPK];
    int q = blockIdx.x, tid = threadIdx.x, lane = tid & 31, wid = tid >> 5;
    const unsigned long long* src = g_cand + (size_t)q * NCAND;

    // each lane holds up to 10 keys in registers (static unroll only)
    unsigned long long k[10];
#pragma unroll
    for (int j = 0; j < 10; j++) {
        int i = tid + j * 128;
        k[j] = (i < NCAND) ? src[i] : ~0ull;
    }

    // 16 warp-min extraction rounds -> per-warp sorted top-16
    for (int s = 0; s < CAND; s++) {
        unsigned long long m = k[0];
#pragma unroll
        for (int j = 1; j < 10; j++) m = ullmin2(m, k[j]);
#pragma unroll
        for (int o = 16; o > 0; o >>= 1)
            m = ullmin2(m, __shfl_xor_sync(0xffffffffu, m, o));
#pragma unroll
        for (int j = 0; j < 10; j++)
            if (k[j] == m) k[j] = ~0ull;
        if (lane == 0) wtop[wid * CAND + s] = m;
    }
    __syncthreads();

    // single-thread 4-way merge of the sorted per-warp lists (smem reads only)
    if (tid == 0) {
        int p0 = 0, p1 = 0, p2 = 0, p3 = 0;
        for (int s = 0; s < CAND; s++) {
            unsigned long long v0 = (p0 < CAND) ? wtop[p0] : ~0ull;
            unsigned long long v1 = (p1 < CAND) ? wtop[CAND + p1] : ~0ull;
            unsigned long long v2 = (p2 < CAND) ? wtop[2 * CAND + p2] : ~0ull;
            unsigned long long v3 = (p3 < CAND) ? wtop[3 * CAND + p3] : ~0ull;
            unsigned long long m01 = ullmin2(v0, v1);
            unsigned long long m23 = ullmin2(v2, v3);
            unsigned long long m = ullmin2(m01, m23);
            if (m == v0) p0++;
            else if (m == v1) p1++;
            else if (m == v2) p2++;
            else p3++;
            cand16[s] = m;
        }
    }
    __syncthreads();

    // exact re-rank: 8 threads per candidate
    {
        int c = tid >> 3, sub = tid & 7;
        unsigned long long key = cand16[c];
        bool valid = key != ~0ull;
        unsigned idx = valid ? (unsigned)(key & 0xffffffffull) : 0u;
        const float4* qv = (const float4*)(g_q + q * D) + sub * 4;
        const float4* rv = (const float4*)(reps + (size_t)idx * D) + sub * 4;
        float dot = 0.f, rn2 = 0.f;
#pragma unroll
        for (int i = 0; i < 4; i++) {
            float4 a = qv[i], b = rv[i];
            dot = fmaf(a.x, b.x, fmaf(a.y, b.y, fmaf(a.z, b.z, fmaf(a.w, b.w, dot))));
            rn2 = fmaf(b.x, b.x, fmaf(b.y, b.y, fmaf(b.z, b.z, fmaf(b.w, b.w, rn2))));
        }
#pragma unroll
        for (int o = 4; o > 0; o >>= 1) {
            dot += __shfl_down_sync(0xffffffffu, dot, o);
            rn2 += __shfl_down_sync(0xffffffffu, rn2, o);
        }
        if (sub == 0) {
            float dx;
            if (valid) {
                float sq = g_qnorm[q] + rn2 - 2.f * dot;
                dx = sqrtf(fmaxf(sq, 1e-12f));
            } else {
                dx = __int_as_float(0x7f800000);
            }
            exactk[c] = pack_key(dx, idx);
        }
    }
    __syncthreads();

    if (tid == 0) {
        for (int i = 1; i < CAND; i++) {
            unsigned long long kk = exactk[i];
            int j = i - 1;
            while (j >= 0 && exactk[j] > kk) { exactk[j + 1] = exactk[j]; j--; }
            exactk[j + 1] = kk;
        }
        float mx = -unpack_val(exactk[0]);
        float sum = 0.f;
#pragma unroll
        for (int s = 0; s < TOPK; s++) {
            float ds = unpack_val(exactk[s]);
            float w = expf(-ds - mx);
            wsh[s] = w; sum += w;
            ish[s] = (unsigned)(exactk[s] & 0xffffffffull);
        }
#pragma unroll
        for (int s = 0; s < TOPK; s++) wsh[s] /= sum;
    }
    __syncthreads();

    if (tid < A_DIM) {
        float o = 0.f;
#pragma unroll
        for (int s = 0; s < TOPK; s++)
            o += wsh[s] * actions[(size_t)ish[s] * A_DIM + tid];
        out[q * A_DIM + tid] = o;
    }
}

extern "C" void kernel_launch(void* const* d_in, const int* in_sizes, int n_in,
                              void* d_out, int out_size) {
    const float* x       = (const float*)d_in[0];
    const float* W_enc   = (const float*)d_in[1];
    const float* b_enc   = (const float*)d_in[2];
    const float* reps    = (const float*)d_in[3];
    const float* actions = (const float*)d_in[4];

    int N = in_sizes[3] / D;
    int ntiles = (N + 127) / 128;

    cudaFuncSetAttribute(dist_topk_kernel,
                         cudaFuncAttributeMaxDynamicSharedMemorySize, SM_TOTAL);

    encoder_part_kernel<<<dim3(B, KSLICES), 128>>>(x, W_enc);
    encoder_reduce_kernel<<<B, 128>>>(b_enc);
    dist_topk_kernel<<<GRID, 256, SM_TOTAL>>>(reps, N, ntiles);
    final_kernel<<<B, 128>>>(reps, actions, (float*)d_out);
}